// round 13
// baseline (speedup 1.0000x reference)
#include <cuda_runtime.h>
#include <cuda_bf16.h>
#include <cfloat>
#include <cstdint>

#define BB 8
#define CC 64
#define NN 4096
#define OO 64
#define KNB 20
#define FULLMASK 0xffffffffu

// Scratch (device globals: allocation-free per harness rules)
__device__ float g_pd[134217728];   // [B*N, N] pairwise "distance", 537MB
__device__ float g_cmax[4194304];   // [B*N, 128] per-32-col-chunk max, 16MB
__device__ float g_sq[32768];       // [B*N] squared norms
__device__ float g_P[2097152];      // [B*N, O]  x·(W1-W2)^T
__device__ float g_Q[2097152];      // [B*N, O]  x·W2^T

#define LDM_X4(r0, r1, r2, r3, addr)                                         \
    asm volatile("ldmatrix.sync.aligned.m8n8.x4.shared.b16 {%0,%1,%2,%3}, [%4];" \
                 : "=r"(r0), "=r"(r1), "=r"(r2), "=r"(r3) : "r"(addr))

#define MMA16816(c, a, b0, b1)                                               \
    asm volatile("mma.sync.aligned.m16n8k16.row.col.f32.bf16.bf16.f32 "      \
                 "{%0,%1,%2,%3}, {%4,%5,%6,%7}, {%8,%9}, {%0,%1,%2,%3};"     \
                 : "+f"((c)[0]), "+f"((c)[1]), "+f"((c)[2]), "+f"((c)[3])    \
                 : "r"((a)[0]), "r"((a)[1]), "r"((a)[2]), "r"((a)[3]),       \
                   "r"(b0), "r"(b1))

// SMEM layout (bytes). 4 bf16 operand tiles [128 rows][64 k] = 16KB each.
// fp32 stage [128][132] = 67584B overlays the operand tiles after the MMA.
#define SM_AH   0
#define SM_AM   16384
#define SM_BH   32768
#define SM_BM   49152
#define SM_SQN  67584
#define SM_SQM  68096
#define SM_TOT  68608
#define STAGE_PITCH 132   // floats; multiple of 4 keeps float4 accesses aligned

__device__ __forceinline__ uint32_t smem_u32(const void* p) {
    uint32_t a;
    asm("{ .reg .u64 t; cvta.to.shared.u64 t, %1; cvt.u32.u64 %0, t; }"
        : "=r"(a) : "l"(p));
    return a;
}

// ---------------------------------------------------------------------------
// Kernel 1: squared norms. sq[b,n] = sum_c x[b,c,n]^2
// ---------------------------------------------------------------------------
__global__ void sq_kernel(const float* __restrict__ x) {
    int t = blockIdx.x * blockDim.x + threadIdx.x;
    int b = t >> 12, n = t & 4095;
    const float* xp = x + (size_t)b * CC * NN + n;
    float s = 0.f;
    #pragma unroll
    for (int c = 0; c < CC; ++c) {
        float v = xp[(size_t)c * NN];
        s = fmaf(v, v, s);
    }
    g_sq[t] = s;
}

// ---------------------------------------------------------------------------
// Kernel 2: P = x·(W1-W2)^T, Q = x·W2^T
// ---------------------------------------------------------------------------
__global__ __launch_bounds__(256) void pq_kernel(const float* __restrict__ x,
                                                 const float* __restrict__ W) {
    __shared__ float Wa[CC][OO + 1];
    __shared__ float Wb[CC][OO + 1];
    __shared__ float xs[CC][4];
    int tid = threadIdx.x;
    #pragma unroll
    for (int i = 0; i < 16; ++i) {
        int fid = tid + i * 256;
        int o = fid >> 6, c = fid & 63;
        float w1 = W[o * 128 + c];
        float w2 = W[o * 128 + 64 + c];
        Wa[c][o] = w1 - w2;
        Wb[c][o] = w2;
    }
    int nbase = blockIdx.x * 4;
    int b = nbase >> 12;
    int nb = nbase & 4095;
    {
        int c = tid >> 2, j = tid & 3;
        xs[c][j] = x[(size_t)b * CC * NN + (size_t)c * NN + nb + j];
    }
    __syncthreads();
    int o = tid & 63, nl = tid >> 6;
    float p = 0.f, q = 0.f;
    #pragma unroll
    for (int c = 0; c < CC; ++c) {
        float xv = xs[c][nl];
        p = fmaf(xv, Wa[c][o], p);
        q = fmaf(xv, Wb[c][o], q);
    }
    size_t g = (size_t)(nbase + nl);
    g_P[g * OO + o] = p;
    g_Q[g * OO + o] = q;
}

// ---------------------------------------------------------------------------
// Kernel 3: pd via 3-term bf16 HMMA split (hh + hm + mh; err <= ~1e-4, used
// for SELECTION only). Triangular grid, single launch (blockIdx.z = b),
// mirror store, per-32-col chunkmax. fp32 staging epilogue (proven in R8).
// ---------------------------------------------------------------------------
__global__ __launch_bounds__(256, 2) void pd_mma3(const float* __restrict__ x) {
    extern __shared__ char sm[];
    uint32_t sb = smem_u32(sm);
    int tid = threadIdx.x, lane = tid & 31, wid = tid >> 5;
    int b = blockIdx.z;

    // tile decode: (nt <= mt), t = mt(mt+1)/2 + nt
    int t = blockIdx.x;
    int mt = (int)((sqrtf(8.f * (float)t + 1.f) - 1.f) * 0.5f);
    while ((mt + 1) * (mt + 2) / 2 <= t) ++mt;
    while (mt * (mt + 1) / 2 > t) --mt;
    int nt = t - mt * (mt + 1) / 2;
    int n0 = nt * 128, m0 = mt * 128;

    // ---- split-load both tiles into h/m bf16 smem (swizzled K-major)
    const float* xb = x + (size_t)b * CC * NN;
    {
        int side = tid >> 7;             // 0: A tile (n-side), 1: B tile
        int row  = tid & 127;
        int p0 = side ? m0 : n0;
        char* hb = sm + (side ? SM_BH : SM_AH);
        #pragma unroll 8
        for (int c = 0; c < CC; c += 2) {
            float v0 = xb[(size_t)c * NN + p0 + row];
            float v1 = xb[(size_t)(c + 1) * NN + p0 + row];
            __nv_bfloat16 h0 = __float2bfloat16(v0), h1 = __float2bfloat16(v1);
            float r0 = v0 - __bfloat162float(h0), r1 = v1 - __bfloat162float(h1);
            __nv_bfloat16 q0 = __float2bfloat16(r0), q1 = __float2bfloat16(r1);
            uint32_t off = (uint32_t)(row * 128 + c * 2);
            off = off ^ ((off >> 3) & 0x70);
            __nv_bfloat162 hh; hh.x = h0; hh.y = h1;
            __nv_bfloat162 mm; mm.x = q0; mm.y = q1;
            *(__nv_bfloat162*)(hb + off)         = hh;
            *(__nv_bfloat162*)(hb + 16384 + off) = mm;
        }
    }
    if (tid < 128)       ((float*)(sm + SM_SQN))[tid]       = g_sq[b * NN + n0 + tid];
    else                 ((float*)(sm + SM_SQM))[tid - 128] = g_sq[b * NN + m0 + (tid - 128)];
    __syncthreads();

    // ---- warp tiling: 2x4 warps, warp tile 64 rows x 32 cols
    int wr = wid >> 2, wc = wid & 3;
    float acc[4][4][4];
    #pragma unroll
    for (int mi = 0; mi < 4; ++mi)
        #pragma unroll
        for (int ni = 0; ni < 4; ++ni)
            #pragma unroll
            for (int q = 0; q < 4; ++q) acc[mi][ni][q] = 0.f;

    // per-lane ldmatrix address components (validated in R8)
    int gA = lane >> 3;
    int rowA_add = (gA & 1) * 8 + (lane & 7);
    int kA_add   = (gA >> 1) * 16;
    uint32_t xorA = (uint32_t)(rowA_add & 7) << 4;
    int gB = lane >> 3;
    int rowB_add = (gB >> 1) * 8 + (lane & 7);
    int kB_add   = (gB & 1) * 16;
    uint32_t xorB = (uint32_t)(rowB_add & 7) << 4;

    const uint32_t aoff[3] = {SM_AH, SM_AH, SM_AM};
    const uint32_t boff[3] = {SM_BH, SM_BM, SM_BH};
    #pragma unroll
    for (int t3 = 0; t3 < 3; ++t3) {
        uint32_t baseA = sb + aoff[t3];
        uint32_t baseB = sb + boff[t3];
        #pragma unroll
        for (int ks = 0; ks < 4; ++ks) {
            int kb = ks * 32;
            uint32_t afr[4][4];
            #pragma unroll
            for (int mi = 0; mi < 4; ++mi) {
                int row = wr * 64 + mi * 16 + rowA_add;
                uint32_t addr = (baseA + (uint32_t)(row * 128 + kb + kA_add)) ^ xorA;
                LDM_X4(afr[mi][0], afr[mi][1], afr[mi][2], afr[mi][3], addr);
            }
            uint32_t bfr[4][2];
            #pragma unroll
            for (int np = 0; np < 2; ++np) {
                int row = wc * 32 + np * 16 + rowB_add;
                uint32_t addr = (baseB + (uint32_t)(row * 128 + kb + kB_add)) ^ xorB;
                LDM_X4(bfr[np * 2][0], bfr[np * 2][1],
                       bfr[np * 2 + 1][0], bfr[np * 2 + 1][1], addr);
            }
            #pragma unroll
            for (int mi = 0; mi < 4; ++mi)
                #pragma unroll
                for (int ni = 0; ni < 4; ++ni)
                    MMA16816(acc[mi][ni], afr[mi], bfr[ni][0], bfr[ni][1]);
        }
    }
    __syncthreads();   // all warps done reading operand smem

    // ---- stage res = 2*acc - sqn - sqm into fp32 smem [128][STAGE_PITCH]
    const float* sqn = (const float*)(sm + SM_SQN);
    const float* sqm = (const float*)(sm + SM_SQM);
    float* stage = (float*)sm;
    {
        int g = lane >> 2, tg = lane & 3;
        #pragma unroll
        for (int mi = 0; mi < 4; ++mi) {
            int r0 = wr * 64 + mi * 16 + g;
            float sn0 = sqn[r0], sn1 = sqn[r0 + 8];
            #pragma unroll
            for (int ni = 0; ni < 4; ++ni) {
                int col = wc * 32 + ni * 8 + tg * 2;
                float sm0 = sqm[col], sm1 = sqm[col + 1];
                float2 u, v;
                u.x = 2.f * acc[mi][ni][0] - sn0 - sm0;
                u.y = 2.f * acc[mi][ni][1] - sn0 - sm1;
                v.x = 2.f * acc[mi][ni][2] - sn1 - sm0;
                v.y = 2.f * acc[mi][ni][3] - sn1 - sm1;
                *(float2*)&stage[r0 * STAGE_PITCH + col]       = u;
                *(float2*)&stage[(r0 + 8) * STAGE_PITCH + col] = v;
            }
        }
    }
    __syncthreads();

    // ---- copy-out: normal rows + chunkmax
    int row = tid >> 1, half = tid & 1;
    float* outp = g_pd + ((size_t)(b * NN + n0 + row)) * NN + m0 + half * 64;
    float* cmn  = g_cmax + (size_t)(b * NN + n0 + row) * 128 + mt * 4 + half * 2;
    {
        float c0 = -FLT_MAX, c1 = -FLT_MAX;
        #pragma unroll
        for (int q = 0; q < 16; ++q) {
            float4 f = *(float4*)&stage[row * STAGE_PITCH + half * 64 + q * 4];
            float mx = fmaxf(fmaxf(f.x, f.y), fmaxf(f.z, f.w));
            if (q < 8) c0 = fmaxf(c0, mx); else c1 = fmaxf(c1, mx);
            *(float4*)&outp[q * 4] = f;
        }
        cmn[0] = c0;
        cmn[1] = c1;
    }

    // ---- mirror (skip on diagonal): transposed read from stage
    if (nt != mt) {
        int mr = row;
        float* outq = g_pd + ((size_t)(b * NN + m0 + mr)) * NN + n0 + half * 64;
        float* cmm  = g_cmax + (size_t)(b * NN + m0 + mr) * 128 + nt * 4 + half * 2;
        float c0 = -FLT_MAX, c1 = -FLT_MAX;
        #pragma unroll 4
        for (int q = 0; q < 16; ++q) {
            float4 f;
            int jb = half * 64 + q * 4;
            f.x = stage[(jb + 0) * STAGE_PITCH + mr];
            f.y = stage[(jb + 1) * STAGE_PITCH + mr];
            f.z = stage[(jb + 2) * STAGE_PITCH + mr];
            f.w = stage[(jb + 3) * STAGE_PITCH + mr];
            float mx = fmaxf(fmaxf(f.x, f.y), fmaxf(f.z, f.w));
            if (q < 8) c0 = fmaxf(c0, mx); else c1 = fmaxf(c1, mx);
            *(float4*)&outq[q * 4] = f;
        }
        cmm[0] = c0;
        cmm[1] = c1;
    }
}

// float -> descending-orderable key (ascending uint sort picks largest first)
__device__ __forceinline__ unsigned int fdesc_key(float v) {
    unsigned int u = __float_as_uint(v);
    u = u ^ (((int)u >> 31) | 0x80000000u);
    return ~u;
}

// ---------------------------------------------------------------------------
// Kernel 4: warp-per-row top-20 via collect-then-sort (R12, proven).
// ---------------------------------------------------------------------------
__global__ __launch_bounds__(256) void topk_fused(
    const float* __restrict__ gamma, const float* __restrict__ beta,
    const float* __restrict__ rmean, const float* __restrict__ rvar,
    float* __restrict__ out)
{
    __shared__ unsigned long long buf[8][64];
    int warp = threadIdx.x >> 5, lane = threadIdx.x & 31;
    int row = blockIdx.x * 8 + warp;
    int b = row >> 12, n = row & 4095;

    const float* cmrow = g_cmax + (size_t)row * 128;
    float cm[4];
    #pragma unroll
    for (int j = 0; j < 4; ++j) cm[j] = __ldg(&cmrow[j * 32 + lane]);
    float lmax = fmaxf(fmaxf(cm[0], cm[1]), fmaxf(cm[2], cm[3]));

    float s = lmax;
    #pragma unroll
    for (int k2 = 2; k2 <= 32; k2 <<= 1) {
        #pragma unroll
        for (int j2 = k2 >> 1; j2 > 0; j2 >>= 1) {
            float o = __shfl_xor_sync(FULLMASK, s, j2);
            bool dirAsc = ((lane & k2) == 0);
            bool upper  = ((lane & j2) == 0);
            float mn = fminf(s, o), mx = fmaxf(s, o);
            s = (dirAsc == upper) ? mn : mx;
        }
    }
    float T0 = __shfl_sync(FULLMASK, s, 32 - KNB);

    const float* rowf = g_pd + (size_t)row * NN;
    unsigned lanelt = (1u << lane) - 1u;

    int cnt = 0;
    #pragma unroll
    for (int j = 0; j < 4; ++j) {
        unsigned cmask = __ballot_sync(FULLMASK, cm[j] >= T0);
        while (cmask) {
            int q = __ffs(cmask) - 1;
            cmask &= cmask - 1;
            int chunk = j * 32 + q;
            float v = __ldg(&rowf[chunk * 32 + lane]);
            unsigned m = __ballot_sync(FULLMASK, v >= T0);
            int pos = cnt + __popc(m & lanelt);
            if (v >= T0 && pos < 64) {
                unsigned long long key =
                    ((unsigned long long)fdesc_key(v) << 32)
                    | (unsigned int)(chunk * 32 + lane);
                buf[warp][pos] = key;
            }
            cnt += __popc(m);
        }
    }

    int li = 0;
    if (cnt <= 64) {
        const unsigned long long PADK = 0xFFFFFFFFFFFFFFFFull;
        unsigned long long e0 = (lane      < cnt) ? buf[warp][lane]      : PADK;
        unsigned long long e1 = (lane + 32 < cnt) ? buf[warp][lane + 32] : PADK;
        #pragma unroll
        for (int k2 = 2; k2 <= 64; k2 <<= 1) {
            #pragma unroll
            for (int j2 = k2 >> 1; j2 > 0; j2 >>= 1) {
                if (j2 == 32) {
                    unsigned long long lo = e0 < e1 ? e0 : e1;
                    unsigned long long hi = e0 < e1 ? e1 : e0;
                    e0 = lo; e1 = hi;
                } else {
                    bool up = ((lane & j2) == 0);
                    {
                        bool asc = ((lane & k2) == 0) || (k2 == 64);
                        unsigned long long o = __shfl_xor_sync(FULLMASK, e0, j2);
                        unsigned long long mn = e0 < o ? e0 : o;
                        unsigned long long mx = e0 < o ? o : e0;
                        e0 = (asc == up) ? mn : mx;
                    }
                    {
                        bool asc = (((lane + 32) & k2) == 0) || (k2 == 64);
                        unsigned long long o = __shfl_xor_sync(FULLMASK, e1, j2);
                        unsigned long long mn = e1 < o ? e1 : o;
                        unsigned long long mx = e1 < o ? o : e1;
                        e1 = (asc == up) ? mn : mx;
                    }
                }
            }
        }
        li = (int)(unsigned int)(e0 & 0xFFFFFFFFull);
    } else {
        float lv = -FLT_MAX;
        float vmin = -FLT_MAX;
        int   minpos = 0;
        #pragma unroll
        for (int j = 0; j < 4; ++j) {
            unsigned cmask = __ballot_sync(FULLMASK, cm[j] >= T0);
            while (cmask) {
                int q = __ffs(cmask) - 1;
                cmask &= cmask - 1;
                float cmv = __shfl_sync(FULLMASK, cm[j], q);
                if (cmv <= vmin && vmin > -FLT_MAX) continue;
                int chunk = j * 32 + q;
                float v = __ldg(&rowf[chunk * 32 + lane]);
                unsigned m = __ballot_sync(FULLMASK, v >= T0 && v > vmin);
                while (m) {
                    int lead = __ffs(m) - 1;
                    float cv = __shfl_sync(FULLMASK, v, lead);
                    int   ci = chunk * 32 + lead;
                    if (lane == minpos) { lv = cv; li = ci; }
                    float tt = (lane < KNB) ? lv : FLT_MAX;
                    #pragma unroll
                    for (int off = 16; off; off >>= 1)
                        tt = fminf(tt, __shfl_xor_sync(FULLMASK, tt, off));
                    vmin = tt;
                    minpos = __ffs(__ballot_sync(FULLMASK,
                                                 lane < KNB && lv == vmin)) - 1;
                    m &= ~(1u << lead);
                    m &= __ballot_sync(FULLMASK, v > vmin);
                }
            }
        }
    }

    float sc1 = gamma[lane]      * rsqrtf(rvar[lane]      + 1e-5f);
    float sc2 = gamma[lane + 32] * rsqrtf(rvar[lane + 32] + 1e-5f);
    float bi1 = beta[lane]      - rmean[lane]      * sc1;
    float bi2 = beta[lane + 32] - rmean[lane + 32] * sc2;
    float p1 = g_P[(size_t)row * OO + lane];
    float p2 = g_P[(size_t)row * OO + lane + 32];
    const float* Qb = g_Q + (size_t)b * NN * OO;

    float m1 = -FLT_MAX, m2 = -FLT_MAX;
    #pragma unroll
    for (int kk = 0; kk < KNB; ++kk) {
        int nid = __shfl_sync(FULLMASK, li, kk);
        const float* Qr = Qb + (size_t)nid * OO;
        float y1 = (p1 + __ldg(&Qr[lane]))      * sc1 + bi1;
        float y2 = (p2 + __ldg(&Qr[lane + 32])) * sc2 + bi2;
        y1 = (y1 >= 0.f) ? y1 : 0.2f * y1;
        y2 = (y2 >= 0.f) ? y2 : 0.2f * y2;
        m1 = fmaxf(m1, y1);
        m2 = fmaxf(m2, y2);
    }
    out[((size_t)b * OO + lane)      * NN + n] = m1;
    out[((size_t)b * OO + lane + 32) * NN + n] = m2;
}

// ---------------------------------------------------------------------------
extern "C" void kernel_launch(void* const* d_in, const int* in_sizes, int n_in,
                              void* d_out, int out_size) {
    const float* x     = (const float*)d_in[0];
    const float* W     = (const float*)d_in[1];
    const float* gamma = (const float*)d_in[2];
    const float* beta  = (const float*)d_in[3];
    const float* rmean = (const float*)d_in[4];
    const float* rvar  = (const float*)d_in[5];
    float* out = (float*)d_out;

    static int inited = 0;
    if (!inited) {
        cudaFuncSetAttribute(pd_mma3, cudaFuncAttributeMaxDynamicSharedMemorySize,
                             SM_TOT);
        inited = 1;
    }

    sq_kernel<<<128, 256>>>(x);
    pq_kernel<<<8192, 256>>>(x, W);
    {
        dim3 grid(528, 1, BB);
        pd_mma3<<<grid, 256, SM_TOT>>>(x);
    }
    topk_fused<<<4096, 256>>>(gamma, beta, rmean, rvar, out);
}

// round 14
// speedup vs baseline: 1.1487x; 1.1487x over previous
#include <cuda_runtime.h>
#include <cfloat>
#include <cstdint>

#define BB 8
#define CC 64
#define NN 4096
#define OO 64
#define KNB 20
#define FULLMASK 0xffffffffu

// Scratch (device globals: allocation-free per harness rules)
__device__ float g_pd[134217728];   // [B*N, N] pairwise "distance", 537MB
__device__ float g_cmax[4194304];   // [B*N, 128] per-32-col-chunk max, 16MB
__device__ float g_sq[32768];       // [B*N] squared norms
__device__ float g_P[2097152];      // [B*N, O]  x·(W1-W2)^T
__device__ float g_Q[2097152];      // [B*N, O]  x·W2^T

// packed f32x2 FMA: d = a*b + d, elementwise on two fp32 lanes (IEEE .rn each)
__device__ __forceinline__ void ffma2(unsigned long long& d,
                                      unsigned long long a,
                                      unsigned long long b) {
    asm("fma.rn.f32x2 %0, %1, %2, %0;" : "+l"(d) : "l"(a), "l"(b));
}
__device__ __forceinline__ unsigned long long dup2(float v) {
    unsigned long long r;
    asm("mov.b64 %0, {%1, %1};" : "=l"(r) : "r"(__float_as_uint(v)));
    return r;
}

// ---------------------------------------------------------------------------
// Kernel 1: squared norms. sq[b,n] = sum_c x[b,c,n]^2 (same FMA order as GEMM)
// ---------------------------------------------------------------------------
__global__ void sq_kernel(const float* __restrict__ x) {
    int t = blockIdx.x * blockDim.x + threadIdx.x;   // 0..32767
    int b = t >> 12, n = t & 4095;
    const float* xp = x + (size_t)b * CC * NN + n;
    float s = 0.f;
    #pragma unroll
    for (int c = 0; c < CC; ++c) {
        float v = xp[(size_t)c * NN];
        s = fmaf(v, v, s);
    }
    g_sq[t] = s;
}

// ---------------------------------------------------------------------------
// Kernel 2: P = x·(W1-W2)^T, Q = x·W2^T   (collapses the edge GEMM)
// ---------------------------------------------------------------------------
__global__ __launch_bounds__(256) void pq_kernel(const float* __restrict__ x,
                                                 const float* __restrict__ W) {
    __shared__ float Wa[CC][OO + 1];
    __shared__ float Wb[CC][OO + 1];
    __shared__ float xs[CC][4];
    int tid = threadIdx.x;
    #pragma unroll
    for (int i = 0; i < 16; ++i) {
        int fid = tid + i * 256;
        int o = fid >> 6, c = fid & 63;
        float w1 = W[o * 128 + c];
        float w2 = W[o * 128 + 64 + c];
        Wa[c][o] = w1 - w2;
        Wb[c][o] = w2;
    }
    int nbase = blockIdx.x * 4;
    int b = nbase >> 12;
    int nb = nbase & 4095;
    {
        int c = tid >> 2, j = tid & 3;
        xs[c][j] = x[(size_t)b * CC * NN + (size_t)c * NN + nb + j];
    }
    __syncthreads();
    int o = tid & 63, nl = tid >> 6;
    float p = 0.f, q = 0.f;
    #pragma unroll
    for (int c = 0; c < CC; ++c) {
        float xv = xs[c][nl];
        p = fmaf(xv, Wa[c][o], p);
        q = fmaf(xv, Wb[c][o], q);
    }
    size_t g = (size_t)(nbase + nl);
    g_P[g * OO + o] = p;
    g_Q[g * OO + o] = q;
}

// ---------------------------------------------------------------------------
// Kernel 3: symmetric pd GEMM (FFMA2 mainloop), triangular grid, single
// launch over all batches. Mirror-stores, per-32-col chunkmax.
// Same FMA c-order as sq_kernel => diagonal exactly 0.  (R6, proven 303us)
// ---------------------------------------------------------------------------
__global__ __launch_bounds__(256) void pd_gemm_sym(const float* __restrict__ x) {
    // linear tile id -> (nt <= mt), t = mt(mt+1)/2 + nt
    int t = blockIdx.x;
    int mt = (int)((sqrtf(8.f * (float)t + 1.f) - 1.f) * 0.5f);
    while ((mt + 1) * (mt + 2) / 2 <= t) ++mt;
    while (mt * (mt + 1) / 2 > t) --mt;
    int nt = t - mt * (mt + 1) / 2;

    __shared__ float As[CC][128];
    __shared__ float Bs[CC][128];
    __shared__ float sqn[128], sqm[128];
    __shared__ float stg[16][128];     // mirror-side chunkmax staging

    int b = blockIdx.z;
    int n0 = nt * 128, m0 = mt * 128;
    const float* xb = x + (size_t)b * CC * NN;
    int tid = threadIdx.x;

    #pragma unroll
    for (int i = 0; i < 8; ++i) {
        int fid = tid + i * 256;
        int c = fid >> 5, v = (fid & 31) << 2;
        *(float4*)&As[c][v] = *(const float4*)&xb[(size_t)c * NN + n0 + v];
        *(float4*)&Bs[c][v] = *(const float4*)&xb[(size_t)c * NN + m0 + v];
    }
    if (tid < 128)       sqn[tid]       = g_sq[b * NN + n0 + tid];
    else                 sqm[tid - 128] = g_sq[b * NN + m0 + (tid - 128)];
    __syncthreads();

    int tx = tid & 15, ty = tid >> 4;

    // packed accumulators: acc2[i][jp] holds cols (2jp, 2jp+1) for row i
    unsigned long long acc2[8][4];
    #pragma unroll
    for (int i = 0; i < 8; ++i)
        #pragma unroll
        for (int jp = 0; jp < 4; ++jp) acc2[i][jp] = 0ull;

    #pragma unroll 4
    for (int c = 0; c < CC; ++c) {
        float ar[8];
        *(float4*)&ar[0] = *(float4*)&As[c][ty * 8];
        *(float4*)&ar[4] = *(float4*)&As[c][ty * 8 + 4];
        ulonglong2 bl = *(ulonglong2*)&Bs[c][tx * 8];
        ulonglong2 bh = *(ulonglong2*)&Bs[c][tx * 8 + 4];
        unsigned long long br2[4] = {bl.x, bl.y, bh.x, bh.y};
        #pragma unroll
        for (int i = 0; i < 8; ++i) {
            unsigned long long ad = dup2(ar[i]);
            #pragma unroll
            for (int jp = 0; jp < 4; ++jp)
                ffma2(acc2[i][jp], ad, br2[jp]);
        }
    }

    // unpack accumulators into acc[i][j]
    float acc[8][8];
    #pragma unroll
    for (int i = 0; i < 8; ++i)
        #pragma unroll
        for (int jp = 0; jp < 4; ++jp) {
            float2 f = *(float2*)&acc2[i][jp];
            acc[i][jp * 2]     = f.x;
            acc[i][jp * 2 + 1] = f.y;
        }

    // normal store: tile [n0.., m0..] + n-side chunk maxima
    float* outp = g_pd + ((size_t)(b * NN + n0)) * NN + m0;
    float* cmn  = g_cmax + ((size_t)(b * NN + n0)) * 128 + (m0 >> 5);
    #pragma unroll
    for (int i = 0; i < 8; ++i) {
        int r = ty * 8 + i;
        float sn = sqn[r];
        float res[8];
        #pragma unroll
        for (int j = 0; j < 8; ++j)
            res[j] = 2.f * acc[i][j] - sn - sqm[tx * 8 + j];
        *(float4*)&outp[(size_t)r * NN + tx * 8]     = *(float4*)&res[0];
        *(float4*)&outp[(size_t)r * NN + tx * 8 + 4] = *(float4*)&res[4];
        float rm = fmaxf(fmaxf(fmaxf(res[0], res[1]), fmaxf(res[2], res[3])),
                         fmaxf(fmaxf(res[4], res[5]), fmaxf(res[6], res[7])));
        rm = fmaxf(rm, __shfl_xor_sync(FULLMASK, rm, 1));
        rm = fmaxf(rm, __shfl_xor_sync(FULLMASK, rm, 2));
        if ((tx & 3) == 0)
            cmn[(size_t)r * 128 + (tx >> 2)] = rm;
    }

    // mirror store: tile [m0.., n0..] + m-side chunk maxima (skip on diagonal)
    if (nt != mt) {
        float* outq = g_pd + ((size_t)(b * NN + m0)) * NN + n0;
        #pragma unroll
        for (int j = 0; j < 8; ++j) {
            int rm = tx * 8 + j;
            float sm = sqm[rm];
            float4 lo, hi;
            lo.x = 2.f * acc[0][j] - sqn[ty * 8 + 0] - sm;
            lo.y = 2.f * acc[1][j] - sqn[ty * 8 + 1] - sm;
            lo.z = 2.f * acc[2][j] - sqn[ty * 8 + 2] - sm;
            lo.w = 2.f * acc[3][j] - sqn[ty * 8 + 3] - sm;
            hi.x = 2.f * acc[4][j] - sqn[ty * 8 + 4] - sm;
            hi.y = 2.f * acc[5][j] - sqn[ty * 8 + 5] - sm;
            hi.z = 2.f * acc[6][j] - sqn[ty * 8 + 6] - sm;
            hi.w = 2.f * acc[7][j] - sqn[ty * 8 + 7] - sm;
            *(float4*)&outq[(size_t)rm * NN + ty * 8]     = lo;
            *(float4*)&outq[(size_t)rm * NN + ty * 8 + 4] = hi;
            float cm = fmaxf(fmaxf(fmaxf(lo.x, lo.y), fmaxf(lo.z, lo.w)),
                             fmaxf(fmaxf(hi.x, hi.y), fmaxf(hi.z, hi.w)));
            stg[ty][rm] = cm;
        }
        __syncthreads();
        if (tid < 128) {
            int col = tid;   // mirror row m0+col
            float* cmm = g_cmax + ((size_t)(b * NN + m0 + col)) * 128 + (n0 >> 5);
            #pragma unroll
            for (int g = 0; g < 4; ++g) {
                float v = fmaxf(fmaxf(stg[g * 4 + 0][col], stg[g * 4 + 1][col]),
                                fmaxf(stg[g * 4 + 2][col], stg[g * 4 + 3][col]));
                cmm[g] = v;
            }
        }
    }
}

// float -> descending-orderable key (ascending uint sort picks largest first)
__device__ __forceinline__ unsigned int fdesc_key(float v) {
    unsigned int u = __float_as_uint(v);
    u = u ^ (((int)u >> 31) | 0x80000000u);
    return ~u;
}

// ---------------------------------------------------------------------------
// Kernel 4: warp-per-row top-20 via collect-then-sort (R12, proven 96us).
// Fused with gather + BN affine + leaky-relu + max-over-k + transposed store.
// ---------------------------------------------------------------------------
__global__ __launch_bounds__(256) void topk_fused(
    const float* __restrict__ gamma, const float* __restrict__ beta,
    const float* __restrict__ rmean, const float* __restrict__ rvar,
    float* __restrict__ out)
{
    __shared__ unsigned long long buf[8][64];
    int warp = threadIdx.x >> 5, lane = threadIdx.x & 31;
    int row = blockIdx.x * 8 + warp;        // 0..32767
    int b = row >> 12, n = row & 4095;

    const float* cmrow = g_cmax + (size_t)row * 128;
    float cm[4];
    #pragma unroll
    for (int j = 0; j < 4; ++j) cm[j] = __ldg(&cmrow[j * 32 + lane]);
    float lmax = fmaxf(fmaxf(cm[0], cm[1]), fmaxf(cm[2], cm[3]));

    // bitonic sort 32 lane-group maxes ascending across lanes
    float s = lmax;
    #pragma unroll
    for (int k2 = 2; k2 <= 32; k2 <<= 1) {
        #pragma unroll
        for (int j2 = k2 >> 1; j2 > 0; j2 >>= 1) {
            float o = __shfl_xor_sync(FULLMASK, s, j2);
            bool dirAsc = ((lane & k2) == 0);
            bool upper  = ((lane & j2) == 0);
            float mn = fminf(s, o), mx = fmaxf(s, o);
            s = (dirAsc == upper) ? mn : mx;
        }
    }
    float T0 = __shfl_sync(FULLMASK, s, 32 - KNB);   // 20th largest group max

    const float* rowf = g_pd + (size_t)row * NN;
    unsigned lanelt = (1u << lane) - 1u;

    // ---- collect candidates v >= T0 into smem buffer (independent loads)
    int cnt = 0;
    #pragma unroll
    for (int j = 0; j < 4; ++j) {
        unsigned cmask = __ballot_sync(FULLMASK, cm[j] >= T0);
        while (cmask) {
            int q = __ffs(cmask) - 1;
            cmask &= cmask - 1;
            int chunk = j * 32 + q;
            float v = __ldg(&rowf[chunk * 32 + lane]);
            unsigned m = __ballot_sync(FULLMASK, v >= T0);
            int pos = cnt + __popc(m & lanelt);
            if (v >= T0 && pos < 64) {
                unsigned long long key =
                    ((unsigned long long)fdesc_key(v) << 32)
                    | (unsigned int)(chunk * 32 + lane);
                buf[warp][pos] = key;
            }
            cnt += __popc(m);
        }
    }

    int li = 0;   // lanes 0..19 will hold the top-20 indices
    if (cnt <= 64) {
        // ---- 64-element bitonic sort (2 keys/lane)
        const unsigned long long PADK = 0xFFFFFFFFFFFFFFFFull;
        unsigned long long e0 = (lane      < cnt) ? buf[warp][lane]      : PADK;
        unsigned long long e1 = (lane + 32 < cnt) ? buf[warp][lane + 32] : PADK;
        #pragma unroll
        for (int k2 = 2; k2 <= 64; k2 <<= 1) {
            #pragma unroll
            for (int j2 = k2 >> 1; j2 > 0; j2 >>= 1) {
                if (j2 == 32) {
                    unsigned long long lo = e0 < e1 ? e0 : e1;
                    unsigned long long hi = e0 < e1 ? e1 : e0;
                    e0 = lo; e1 = hi;
                } else {
                    bool up = ((lane & j2) == 0);
                    {
                        bool asc = ((lane & k2) == 0) || (k2 == 64);
                        unsigned long long o = __shfl_xor_sync(FULLMASK, e0, j2);
                        unsigned long long mn = e0 < o ? e0 : o;
                        unsigned long long mx = e0 < o ? o : e0;
                        e0 = (asc == up) ? mn : mx;
                    }
                    {
                        bool asc = (((lane + 32) & k2) == 0) || (k2 == 64);
                        unsigned long long o = __shfl_xor_sync(FULLMASK, e1, j2);
                        unsigned long long mn = e1 < o ? e1 : o;
                        unsigned long long mx = e1 < o ? o : e1;
                        e1 = (asc == up) ? mn : mx;
                    }
                }
            }
        }
        li = (int)(unsigned int)(e0 & 0xFFFFFFFFull);
    } else {
        // ---- rare overflow: exact sequential insert scan (proven path)
        float lv = -FLT_MAX;
        float vmin = -FLT_MAX;
        int   minpos = 0;
        #pragma unroll
        for (int j = 0; j < 4; ++j) {
            unsigned cmask = __ballot_sync(FULLMASK, cm[j] >= T0);
            while (cmask) {
                int q = __ffs(cmask) - 1;
                cmask &= cmask - 1;
                float cmv = __shfl_sync(FULLMASK, cm[j], q);
                if (cmv <= vmin && vmin > -FLT_MAX) continue;
                int chunk = j * 32 + q;
                float v = __ldg(&rowf[chunk * 32 + lane]);
                unsigned m = __ballot_sync(FULLMASK, v >= T0 && v > vmin);
                while (m) {
                    int lead = __ffs(m) - 1;
                    float cv = __shfl_sync(FULLMASK, v, lead);
                    int   ci = chunk * 32 + lead;
                    if (lane == minpos) { lv = cv; li = ci; }
                    float tt = (lane < KNB) ? lv : FLT_MAX;
                    #pragma unroll
                    for (int off = 16; off; off >>= 1)
                        tt = fminf(tt, __shfl_xor_sync(FULLMASK, tt, off));
                    vmin = tt;
                    minpos = __ffs(__ballot_sync(FULLMASK,
                                                 lane < KNB && lv == vmin)) - 1;
                    m &= ~(1u << lead);
                    m &= __ballot_sync(FULLMASK, v > vmin);
                }
            }
        }
    }

    // ---- fused epilogue: out[b,o,n] = max_k leaky(BN(P[row,o] + Q[idx_k,o]))
    float sc1 = gamma[lane]      * rsqrtf(rvar[lane]      + 1e-5f);
    float sc2 = gamma[lane + 32] * rsqrtf(rvar[lane + 32] + 1e-5f);
    float bi1 = beta[lane]      - rmean[lane]      * sc1;
    float bi2 = beta[lane + 32] - rmean[lane + 32] * sc2;
    float p1 = g_P[(size_t)row * OO + lane];
    float p2 = g_P[(size_t)row * OO + lane + 32];
    const float* Qb = g_Q + (size_t)b * NN * OO;

    float m1 = -FLT_MAX, m2 = -FLT_MAX;
    #pragma unroll
    for (int kk = 0; kk < KNB; ++kk) {
        int nid = __shfl_sync(FULLMASK, li, kk);
        const float* Qr = Qb + (size_t)nid * OO;
        float y1 = (p1 + __ldg(&Qr[lane]))      * sc1 + bi1;
        float y2 = (p2 + __ldg(&Qr[lane + 32])) * sc2 + bi2;
        y1 = (y1 >= 0.f) ? y1 : 0.2f * y1;
        y2 = (y2 >= 0.f) ? y2 : 0.2f * y2;
        m1 = fmaxf(m1, y1);
        m2 = fmaxf(m2, y2);
    }
    out[((size_t)b * OO + lane)      * NN + n] = m1;
    out[((size_t)b * OO + lane + 32) * NN + n] = m2;
}

// ---------------------------------------------------------------------------
extern "C" void kernel_launch(void* const* d_in, const int* in_sizes, int n_in,
                              void* d_out, int out_size) {
    const float* x     = (const float*)d_in[0];
    const float* W     = (const float*)d_in[1];
    const float* gamma = (const float*)d_in[2];
    const float* beta  = (const float*)d_in[3];
    const float* rmean = (const float*)d_in[4];
    const float* rvar  = (const float*)d_in[5];
    float* out = (float*)d_out;

    sq_kernel<<<128, 256>>>(x);
    pq_kernel<<<8192, 256>>>(x, W);
    {
        dim3 grid(528, 1, BB);
        pd_gemm_sym<<<grid, 256>>>(x);
    }
    topk_fused<<<4096, 256>>>(gamma, beta, rmean, rvar, out);
}

// round 15
// speedup vs baseline: 1.1999x; 1.0446x over previous
#include <cuda_runtime.h>
#include <cfloat>
#include <cstdint>

#define BB 8
#define CC 64
#define NN 4096
#define OO 64
#define KNB 20
#define FULLMASK 0xffffffffu

// Scratch (device globals: allocation-free per harness rules)
__device__ float g_pd[134217728];   // [B*N, N] pairwise "distance", 537MB
__device__ float g_cmax[4194304];   // [B*N, 128] per-32-col-chunk max, 16MB
__device__ float g_sq[32768];       // [B*N] squared norms
__device__ float g_P[2097152];      // [B*N, O]  x·(W1-W2)^T
__device__ float g_Q[2097152];      // [B*N, O]  x·W2^T

// packed f32x2 FMA: d = a*b + d, elementwise on two fp32 lanes (IEEE .rn each)
__device__ __forceinline__ void ffma2(unsigned long long& d,
                                      unsigned long long a,
                                      unsigned long long b) {
    asm("fma.rn.f32x2 %0, %1, %2, %0;" : "+l"(d) : "l"(a), "l"(b));
}
__device__ __forceinline__ unsigned long long dup2(float v) {
    unsigned long long r;
    asm("mov.b64 %0, {%1, %1};" : "=l"(r) : "r"(__float_as_uint(v)));
    return r;
}

// ---------------------------------------------------------------------------
// Kernel 1: squared norms. sq[b,n] = sum_c x[b,c,n]^2 (same FMA order as GEMM)
// ---------------------------------------------------------------------------
__global__ void sq_kernel(const float* __restrict__ x) {
    int t = blockIdx.x * blockDim.x + threadIdx.x;   // 0..32767
    int b = t >> 12, n = t & 4095;
    const float* xp = x + (size_t)b * CC * NN + n;
    float s = 0.f;
    #pragma unroll
    for (int c = 0; c < CC; ++c) {
        float v = xp[(size_t)c * NN];
        s = fmaf(v, v, s);
    }
    g_sq[t] = s;
}

// ---------------------------------------------------------------------------
// Kernel 2: P = x·(W1-W2)^T, Q = x·W2^T   (collapses the edge GEMM)
// ---------------------------------------------------------------------------
__global__ __launch_bounds__(256) void pq_kernel(const float* __restrict__ x,
                                                 const float* __restrict__ W) {
    __shared__ float Wa[CC][OO + 1];
    __shared__ float Wb[CC][OO + 1];
    __shared__ float xs[CC][4];
    int tid = threadIdx.x;
    #pragma unroll
    for (int i = 0; i < 16; ++i) {
        int fid = tid + i * 256;
        int o = fid >> 6, c = fid & 63;
        float w1 = W[o * 128 + c];
        float w2 = W[o * 128 + 64 + c];
        Wa[c][o] = w1 - w2;
        Wb[c][o] = w2;
    }
    int nbase = blockIdx.x * 4;
    int b = nbase >> 12;
    int nb = nbase & 4095;
    {
        int c = tid >> 2, j = tid & 3;
        xs[c][j] = x[(size_t)b * CC * NN + (size_t)c * NN + nb + j];
    }
    __syncthreads();
    int o = tid & 63, nl = tid >> 6;
    float p = 0.f, q = 0.f;
    #pragma unroll
    for (int c = 0; c < CC; ++c) {
        float xv = xs[c][nl];
        p = fmaf(xv, Wa[c][o], p);
        q = fmaf(xv, Wb[c][o], q);
    }
    size_t g = (size_t)(nbase + nl);
    g_P[g * OO + o] = p;
    g_Q[g * OO + o] = q;
}

// ---------------------------------------------------------------------------
// Kernel 3: symmetric pd GEMM (FFMA2 mainloop), triangular grid, single
// launch over all batches. Normal store coalesced from registers; mirror
// store staged through reused operand smem (swizzled) so it is coalesced too.
// Same FMA c-order as sq_kernel => diagonal exactly 0.
// ---------------------------------------------------------------------------
__global__ __launch_bounds__(256) void pd_gemm_sym(const float* __restrict__ x) {
    // smem union: As [0,32768), Bs [32768,65536); after mainloop the region
    // [0,67584) is reused as the fp32 mirror stage [128 rows][132 floats].
    __shared__ __align__(16) char smem_all[68608];
    float* As  = (float*)smem_all;               // As[c][v] = As[c*128+v]
    float* Bs  = (float*)(smem_all + 32768);
    float* sqn = (float*)(smem_all + 67584);
    float* sqm = (float*)(smem_all + 68096);

    // linear tile id -> (nt <= mt), t = mt(mt+1)/2 + nt
    int t = blockIdx.x;
    int mt = (int)((sqrtf(8.f * (float)t + 1.f) - 1.f) * 0.5f);
    while ((mt + 1) * (mt + 2) / 2 <= t) ++mt;
    while (mt * (mt + 1) / 2 > t) --mt;
    int nt = t - mt * (mt + 1) / 2;

    int b = blockIdx.z;
    int n0 = nt * 128, m0 = mt * 128;
    const float* xb = x + (size_t)b * CC * NN;
    int tid = threadIdx.x;

    #pragma unroll
    for (int i = 0; i < 8; ++i) {
        int fid = tid + i * 256;
        int c = fid >> 5, v = (fid & 31) << 2;
        *(float4*)&As[c * 128 + v] = *(const float4*)&xb[(size_t)c * NN + n0 + v];
        *(float4*)&Bs[c * 128 + v] = *(const float4*)&xb[(size_t)c * NN + m0 + v];
    }
    if (tid < 128)       sqn[tid]       = g_sq[b * NN + n0 + tid];
    else                 sqm[tid - 128] = g_sq[b * NN + m0 + (tid - 128)];
    __syncthreads();

    int tx = tid & 15, ty = tid >> 4;

    // packed accumulators: acc2[i][jp] holds cols (2jp, 2jp+1) for row i
    unsigned long long acc2[8][4];
    #pragma unroll
    for (int i = 0; i < 8; ++i)
        #pragma unroll
        for (int jp = 0; jp < 4; ++jp) acc2[i][jp] = 0ull;

    #pragma unroll 4
    for (int c = 0; c < CC; ++c) {
        float ar[8];
        *(float4*)&ar[0] = *(float4*)&As[c * 128 + ty * 8];
        *(float4*)&ar[4] = *(float4*)&As[c * 128 + ty * 8 + 4];
        ulonglong2 bl = *(ulonglong2*)&Bs[c * 128 + tx * 8];
        ulonglong2 bh = *(ulonglong2*)&Bs[c * 128 + tx * 8 + 4];
        unsigned long long br2[4] = {bl.x, bl.y, bh.x, bh.y};
        #pragma unroll
        for (int i = 0; i < 8; ++i) {
            unsigned long long ad = dup2(ar[i]);
            #pragma unroll
            for (int jp = 0; jp < 4; ++jp)
                ffma2(acc2[i][jp], ad, br2[jp]);
        }
    }

    // unpack accumulators into acc[i][j]
    float acc[8][8];
    #pragma unroll
    for (int i = 0; i < 8; ++i)
        #pragma unroll
        for (int jp = 0; jp < 4; ++jp) {
            float2 f = *(float2*)&acc2[i][jp];
            acc[i][jp * 2]     = f.x;
            acc[i][jp * 2 + 1] = f.y;
        }

    // ---- normal store: tile [n0.., m0..] + n-side chunk maxima (coalesced)
    float* outp = g_pd + ((size_t)(b * NN + n0)) * NN + m0;
    float* cmn  = g_cmax + ((size_t)(b * NN + n0)) * 128 + (m0 >> 5);
    #pragma unroll
    for (int i = 0; i < 8; ++i) {
        int r = ty * 8 + i;
        float sn = sqn[r];
        float res[8];
        #pragma unroll
        for (int j = 0; j < 8; ++j)
            res[j] = 2.f * acc[i][j] - sn - sqm[tx * 8 + j];
        *(float4*)&outp[(size_t)r * NN + tx * 8]     = *(float4*)&res[0];
        *(float4*)&outp[(size_t)r * NN + tx * 8 + 4] = *(float4*)&res[4];
        float rm = fmaxf(fmaxf(fmaxf(res[0], res[1]), fmaxf(res[2], res[3])),
                         fmaxf(fmaxf(res[4], res[5]), fmaxf(res[6], res[7])));
        rm = fmaxf(rm, __shfl_xor_sync(FULLMASK, rm, 1));
        rm = fmaxf(rm, __shfl_xor_sync(FULLMASK, rm, 2));
        if ((tx & 3) == 0)
            cmn[(size_t)r * 128 + (tx >> 2)] = rm;
    }

    // ---- mirror: stage transposed tile in smem (swizzled), then coalesced
    //      copy-out + m-side chunkmax. Skip on diagonal tiles.
    if (nt != mt) {
        __syncthreads();     // all warps done reading As/Bs
        float* stage = (float*)smem_all;   // [128 rows][132 floats], swizzled slots
        #pragma unroll
        for (int j = 0; j < 8; ++j) {
            int rm = tx * 8 + j;           // mirror row (original col index)
            float smv = sqm[rm];
            float tmp[8];
            #pragma unroll
            for (int i = 0; i < 8; ++i)
                tmp[i] = 2.f * acc[i][j] - sqn[ty * 8 + i] - smv;
            // swizzled float4 slots: physical = logical ^ ((row>>3)<<1)
            int sw = (tx & 15) << 1;       // rm>>3 == tx
            int s0 = (ty * 2)     ^ sw;
            int s1 = (ty * 2 + 1) ^ sw;
            *(float4*)&stage[rm * 132 + s0 * 4] = *(float4*)&tmp[0];
            *(float4*)&stage[rm * 132 + s1 * 4] = *(float4*)&tmp[4];
        }
        __syncthreads();
        int wid2 = tid >> 5, lane = tid & 31;
        #pragma unroll 4
        for (int it = 0; it < 16; ++it) {
            int mr = it * 8 + wid2;
            int ps = lane ^ (((mr >> 3) & 15) << 1);
            float4 f = *(float4*)&stage[mr * 132 + ps * 4];
            float mx = fmaxf(fmaxf(f.x, f.y), fmaxf(f.z, f.w));
            mx = fmaxf(mx, __shfl_xor_sync(FULLMASK, mx, 1));
            mx = fmaxf(mx, __shfl_xor_sync(FULLMASK, mx, 2));
            mx = fmaxf(mx, __shfl_xor_sync(FULLMASK, mx, 4));
            *(float4*)&g_pd[((size_t)(b * NN + m0 + mr)) * NN + n0 + lane * 4] = f;
            if ((lane & 7) == 0)
                g_cmax[(size_t)(b * NN + m0 + mr) * 128 + nt * 4 + (lane >> 3)] = mx;
        }
    }
}

// float -> descending-orderable key (ascending uint sort picks largest first)
__device__ __forceinline__ unsigned int fdesc_key(float v) {
    unsigned int u = __float_as_uint(v);
    u = u ^ (((int)u >> 31) | 0x80000000u);
    return ~u;
}

// ---------------------------------------------------------------------------
// Kernel 4: warp-per-row top-20 via collect-then-sort (R12, proven 96us).
// Fused with gather + BN affine + leaky-relu + max-over-k + transposed store.
// ---------------------------------------------------------------------------
__global__ __launch_bounds__(256) void topk_fused(
    const float* __restrict__ gamma, const float* __restrict__ beta,
    const float* __restrict__ rmean, const float* __restrict__ rvar,
    float* __restrict__ out)
{
    __shared__ unsigned long long buf[8][64];
    int warp = threadIdx.x >> 5, lane = threadIdx.x & 31;
    int row = blockIdx.x * 8 + warp;        // 0..32767
    int b = row >> 12, n = row & 4095;

    const float* cmrow = g_cmax + (size_t)row * 128;
    float cm[4];
    #pragma unroll
    for (int j = 0; j < 4; ++j) cm[j] = __ldg(&cmrow[j * 32 + lane]);
    float lmax = fmaxf(fmaxf(cm[0], cm[1]), fmaxf(cm[2], cm[3]));

    // bitonic sort 32 lane-group maxes ascending across lanes
    float s = lmax;
    #pragma unroll
    for (int k2 = 2; k2 <= 32; k2 <<= 1) {
        #pragma unroll
        for (int j2 = k2 >> 1; j2 > 0; j2 >>= 1) {
            float o = __shfl_xor_sync(FULLMASK, s, j2);
            bool dirAsc = ((lane & k2) == 0);
            bool upper  = ((lane & j2) == 0);
            float mn = fminf(s, o), mx = fmaxf(s, o);
            s = (dirAsc == upper) ? mn : mx;
        }
    }
    float T0 = __shfl_sync(FULLMASK, s, 32 - KNB);   // 20th largest group max

    const float* rowf = g_pd + (size_t)row * NN;
    unsigned lanelt = (1u << lane) - 1u;

    // ---- collect candidates v >= T0 into smem buffer (independent loads)
    int cnt = 0;
    #pragma unroll
    for (int j = 0; j < 4; ++j) {
        unsigned cmask = __ballot_sync(FULLMASK, cm[j] >= T0);
        while (cmask) {
            int q = __ffs(cmask) - 1;
            cmask &= cmask - 1;
            int chunk = j * 32 + q;
            float v = __ldg(&rowf[chunk * 32 + lane]);
            unsigned m = __ballot_sync(FULLMASK, v >= T0);
            int pos = cnt + __popc(m & lanelt);
            if (v >= T0 && pos < 64) {
                unsigned long long key =
                    ((unsigned long long)fdesc_key(v) << 32)
                    | (unsigned int)(chunk * 32 + lane);
                buf[warp][pos] = key;
            }
            cnt += __popc(m);
        }
    }

    int li = 0;   // lanes 0..19 will hold the top-20 indices
    if (cnt <= 64) {
        // ---- 64-element bitonic sort (2 keys/lane)
        const unsigned long long PADK = 0xFFFFFFFFFFFFFFFFull;
        unsigned long long e0 = (lane      < cnt) ? buf[warp][lane]      : PADK;
        unsigned long long e1 = (lane + 32 < cnt) ? buf[warp][lane + 32] : PADK;
        #pragma unroll
        for (int k2 = 2; k2 <= 64; k2 <<= 1) {
            #pragma unroll
            for (int j2 = k2 >> 1; j2 > 0; j2 >>= 1) {
                if (j2 == 32) {
                    unsigned long long lo = e0 < e1 ? e0 : e1;
                    unsigned long long hi = e0 < e1 ? e1 : e0;
                    e0 = lo; e1 = hi;
                } else {
                    bool up = ((lane & j2) == 0);
                    {
                        bool asc = ((lane & k2) == 0) || (k2 == 64);
                        unsigned long long o = __shfl_xor_sync(FULLMASK, e0, j2);
                        unsigned long long mn = e0 < o ? e0 : o;
                        unsigned long long mx = e0 < o ? o : e0;
                        e0 = (asc == up) ? mn : mx;
                    }
                    {
                        bool asc = (((lane + 32) & k2) == 0) || (k2 == 64);
                        unsigned long long o = __shfl_xor_sync(FULLMASK, e1, j2);
                        unsigned long long mn = e1 < o ? e1 : o;
                        unsigned long long mx = e1 < o ? o : e1;
                        e1 = (asc == up) ? mn : mx;
                    }
                }
            }
        }
        li = (int)(unsigned int)(e0 & 0xFFFFFFFFull);
    } else {
        // ---- rare overflow: exact sequential insert scan (proven path)
        float lv = -FLT_MAX;
        float vmin = -FLT_MAX;
        int   minpos = 0;
        #pragma unroll
        for (int j = 0; j < 4; ++j) {
            unsigned cmask = __ballot_sync(FULLMASK, cm[j] >= T0);
            while (cmask) {
                int q = __ffs(cmask) - 1;
                cmask &= cmask - 1;
                float cmv = __shfl_sync(FULLMASK, cm[j], q);
                if (cmv <= vmin && vmin > -FLT_MAX) continue;
                int chunk = j * 32 + q;
                float v = __ldg(&rowf[chunk * 32 + lane]);
                unsigned m = __ballot_sync(FULLMASK, v >= T0 && v > vmin);
                while (m) {
                    int lead = __ffs(m) - 1;
                    float cv = __shfl_sync(FULLMASK, v, lead);
                    int   ci = chunk * 32 + lead;
                    if (lane == minpos) { lv = cv; li = ci; }
                    float tt = (lane < KNB) ? lv : FLT_MAX;
                    #pragma unroll
                    for (int off = 16; off; off >>= 1)
                        tt = fminf(tt, __shfl_xor_sync(FULLMASK, tt, off));
                    vmin = tt;
                    minpos = __ffs(__ballot_sync(FULLMASK,
                                                 lane < KNB && lv == vmin)) - 1;
                    m &= ~(1u << lead);
                    m &= __ballot_sync(FULLMASK, v > vmin);
                }
            }
        }
    }

    // ---- fused epilogue: out[b,o,n] = max_k leaky(BN(P[row,o] + Q[idx_k,o]))
    float sc1 = gamma[lane]      * rsqrtf(rvar[lane]      + 1e-5f);
    float sc2 = gamma[lane + 32] * rsqrtf(rvar[lane + 32] + 1e-5f);
    float bi1 = beta[lane]      - rmean[lane]      * sc1;
    float bi2 = beta[lane + 32] - rmean[lane + 32] * sc2;
    float p1 = g_P[(size_t)row * OO + lane];
    float p2 = g_P[(size_t)row * OO + lane + 32];
    const float* Qb = g_Q + (size_t)b * NN * OO;

    float m1 = -FLT_MAX, m2 = -FLT_MAX;
    #pragma unroll
    for (int kk = 0; kk < KNB; ++kk) {
        int nid = __shfl_sync(FULLMASK, li, kk);
        const float* Qr = Qb + (size_t)nid * OO;
        float y1 = (p1 + __ldg(&Qr[lane]))      * sc1 + bi1;
        float y2 = (p2 + __ldg(&Qr[lane + 32])) * sc2 + bi2;
        y1 = (y1 >= 0.f) ? y1 : 0.2f * y1;
        y2 = (y2 >= 0.f) ? y2 : 0.2f * y2;
        m1 = fmaxf(m1, y1);
        m2 = fmaxf(m2, y2);
    }
    out[((size_t)b * OO + lane)      * NN + n] = m1;
    out[((size_t)b * OO + lane + 32) * NN + n] = m2;
}

// ---------------------------------------------------------------------------
extern "C" void kernel_launch(void* const* d_in, const int* in_sizes, int n_in,
                              void* d_out, int out_size) {
    const float* x     = (const float*)d_in[0];
    const float* W     = (const float*)d_in[1];
    const float* gamma = (const float*)d_in[2];
    const float* beta  = (const float*)d_in[3];
    const float* rmean = (const float*)d_in[4];
    const float* rvar  = (const float*)d_in[5];
    float* out = (float*)d_out;

    sq_kernel<<<128, 256>>>(x);
    pq_kernel<<<8192, 256>>>(x, W);
    {
        dim3 grid(528, 1, BB);
        pd_gemm_sym<<<grid, 256>>>(x);
    }
    topk_fused<<<4096, 256>>>(gamma, beta, rmean, rvar, out);
}